// round 16
// baseline (speedup 1.0000x reference)
#include <cuda_runtime.h>
#include <cuda_bf16.h>
#include <stdint.h>
#include <math.h>

#define T_LEN 16384
#define NB 4

static __device__ __forceinline__ float sigmoidf_(float v) {
    return 1.0f / (1.0f + __expf(-v));
}

#define SQRT_HALF_F 0.70710678118654752f

// bf16 HMMA m16n8k16 (base-target PTX)
static __device__ __forceinline__ void mma_bf16(
    float* d, uint32_t a0, uint32_t a1, uint32_t a2, uint32_t a3,
    uint32_t b0, uint32_t b1)
{
    asm volatile(
        "mma.sync.aligned.m16n8k16.row.col.f32.bf16.bf16.f32 "
        "{%0,%1,%2,%3}, {%4,%5,%6,%7}, {%8,%9}, {%0,%1,%2,%3};"
        : "+f"(d[0]), "+f"(d[1]), "+f"(d[2]), "+f"(d[3])
        : "r"(a0), "r"(a1), "r"(a2), "r"(a3), "r"(b0), "r"(b1));
}
// ldmatrix x4 (base PTX sm_75+)
static __device__ __forceinline__ void ldsm_x4(uint32_t* r, uint32_t addr) {
    asm volatile(
        "ldmatrix.sync.aligned.m8n8.x4.shared.b16 {%0,%1,%2,%3}, [%4];"
        : "=r"(r[0]), "=r"(r[1]), "=r"(r[2]), "=r"(r[3]) : "r"(addr));
}
static __device__ __forceinline__ uint32_t pk_bf2(float a, float b) {
    __nv_bfloat162 t;
    t.x = __float2bfloat16(a);
    t.y = __float2bfloat16(b);
    return *(uint32_t*)&t;
}
static __device__ __forceinline__ uint32_t smem_u32(const void* p) {
    uint32_t a;
    asm("{ .reg .u64 t; cvta.to.shared.u64 t, %1; cvt.u32.u64 %0, t; }"
        : "=r"(a) : "l"(p));
    return a;
}
// split float pair into hi/lo bf16 packed words
static __device__ __forceinline__ void split2(float a, float b,
                                              uint32_t& hi, uint32_t& lo) {
    __nv_bfloat16 h0 = __float2bfloat16(a);
    __nv_bfloat16 h1 = __float2bfloat16(b);
    hi = pk_bf2(a, b);
    lo = pk_bf2(a - __bfloat162float(h0), b - __bfloat162float(h1));
}

// ---------------- scratch (allocation-free: __device__ globals) ----------------
__device__ float g_h[2][NB * 64 * T_LEN];     // residual ping-pong (fp32)
__device__ __nv_bfloat16 g_hbh[2][NB * 64 * T_LEN];   // h bf16 hi ping-pong
__device__ __nv_bfloat16 g_hbl[2][NB * 64 * T_LEN];   // h bf16 lo
__device__ float g_skip[NB * 256 * T_LEN];    // skip accumulator (written once)
__device__ float g_tmp[NB * 256 * T_LEN];     // final intermediate
// z storage (all layers), bf16 hi/lo, layout [((l*NB + b)*64 + ch)][t]
__device__ __nv_bfloat16 g_zbh[20 * NB * 64 * T_LEN];
__device__ __nv_bfloat16 g_zbl[20 * NB * 64 * T_LEN];
// prepped conditioning bf16 hi/lo, [b][ch][t] (same layout as c)
__device__ __nv_bfloat16 g_cbh[NB * 80 * T_LEN];
__device__ __nv_bfloat16 g_cbl[NB * 80 * T_LEN];
// prepped dense weights: [stage][chunk][oc*136 + klocal]
__device__ __nv_bfloat16 g_dwh[2][2][256 * 136];
__device__ __nv_bfloat16 g_dwl[2][2][256 * 136];
// prepped scaled skip weights: [chunk 0..9][sc*136 + klocal], combined bias
__device__ __nv_bfloat16 g_swh[10][256 * 136];
__device__ __nv_bfloat16 g_swl[10][256 * 136];
__device__ float g_bskc[256];

// telescoped scale: s_l multiplied by sqrt(1/2)^e, e = 19 for l=0, 20-l for l>=1
static __device__ __forceinline__ float skip_scale(int l) {
    int e = (l == 0) ? 19 : (20 - l);
    return exp2f(-0.5f * (float)e);
}

// =======================================================================
// Kernel 0a: prep dense weights
// =======================================================================
__global__ void prep_dense_kernel(const float* __restrict__ W1,
                                  const float* __restrict__ W2)
{
    int i = blockIdx.x * blockDim.x + threadIdx.x;
    if (i >= 2 * 256 * 256) return;
    int stage = i >> 16;
    int oc = (i >> 8) & 255;
    int k = i & 255;
    float w = (stage ? W2 : W1)[oc * 256 + k];
    __nv_bfloat16 wh = __float2bfloat16(w);
    int chunk = k >> 7, kl = k & 127;
    g_dwh[stage][chunk][oc * 136 + kl] = wh;
    g_dwl[stage][chunk][oc * 136 + kl] = __float2bfloat16(w - __bfloat162float(wh));
}

// =======================================================================
// Kernel 0b: prep scaled skip weights + combined bias
// =======================================================================
__global__ void prep_skipw_kernel(const float* __restrict__ W_skip,
                                  const float* __restrict__ b_skip)
{
    int i = blockIdx.x * blockDim.x + threadIdx.x;
    if (i < 256 * 1280) {
        int sc = i / 1280, k = i - sc * 1280;
        int l = k >> 6, r = k & 63;
        float w = W_skip[l * 16384 + sc * 64 + r] * skip_scale(l);
        __nv_bfloat16 wh = __float2bfloat16(w);
        int chunk = k >> 7, kl = k & 127;
        g_swh[chunk][sc * 136 + kl] = wh;
        g_swl[chunk][sc * 136 + kl] = __float2bfloat16(w - __bfloat162float(wh));
    }
    if (i < 256) {
        float s = 0.f;
        for (int l = 0; l < 20; l++)
            s += skip_scale(l) * b_skip[l * 256 + i];
        g_bskc[i] = s;
    }
}

// =======================================================================
// Kernel 0c: prep conditioning c -> bf16 hi/lo (same [b][ch][t] layout)
// =======================================================================
__global__ void prep_c_kernel(const float* __restrict__ c)
{
    size_t i = ((size_t)blockIdx.x * blockDim.x + threadIdx.x) * 4;
    if (i >= (size_t)NB * 80 * T_LEN) return;
    float4 v = *(const float4*)(c + i);
    uint32_t h0, l0, h1, l1;
    split2(v.x, v.y, h0, l0);
    split2(v.z, v.w, h1, l1);
    *(uint2*)(g_cbh + i) = make_uint2(h0, h1);
    *(uint2*)(g_cbl + i) = make_uint2(l0, l1);
}

// =======================================================================
// Kernel 1 (HMMA + ldmatrix): first conv; also emits h as bf16 hi/lo.
// =======================================================================
#define FIRST_SMEM 209920
__global__ __launch_bounds__(512) void first_hmma_kernel(
    const float* __restrict__ x, const float* __restrict__ Wf,
    const float* __restrict__ bf)
{
    extern __shared__ float smf[];
    char* smem = (char*)smf;

    int tid = threadIdx.x;
    int lane = tid & 31, warp = tid >> 5;

    float* bb = smf;    // 64
    __nv_bfloat16* AhS = (__nv_bfloat16*)(smem + 1024);
    __nv_bfloat16* AlS = (__nv_bfloat16*)(smem + 70656);
    __nv_bfloat16* BhS = (__nv_bfloat16*)(smem + 140288);
    __nv_bfloat16* BlS = (__nv_bfloat16*)(smem + 175104);
    const uint32_t A_LO = 69632, B_LO = 34816;

    if (tid < 64) bb[tid] = bf[tid];
    for (int i = tid; i < 64 * 512; i += 512) {
        int oc = i >> 9, k = i & 511;
        int chunk = k >> 7, kl = k & 127;
        float w = Wf[oc * 512 + k];
        __nv_bfloat16 wh = __float2bfloat16(w);
        AhS[(chunk * 64 + oc) * 136 + kl] = wh;
        AlS[(chunk * 64 + oc) * 136 + kl] = __float2bfloat16(w - __bfloat162float(wh));
    }
    __syncthreads();

    int mt = warp & 3;
    int tg = warp >> 2;
    int q = (lane & 3) * 2;
    int rl = lane >> 2;

    uint32_t sb = smem_u32(smem);
    uint32_t aBase = sb + 1024 +
        (uint32_t)(((mt * 16 + (lane & 15)) * 136 + (lane >> 4) * 8) * 2);
    uint32_t bBase[2];
#pragma unroll
    for (int p = 0; p < 2; p++) {
        int n = tg * 32 + ((lane >> 4) & 1) * 8 + (lane & 7) + 16 * p;
        bBase[p] = sb + 140288 + (uint32_t)((n * 136) * 2 + (lane & 8) * 2);
    }

    for (int tile = blockIdx.x; tile < NB * 128; tile += gridDim.x) {
        int b = tile >> 7;
        int t0 = (tile & 127) << 7;

        float d[4][4];
#pragma unroll
        for (int nt = 0; nt < 4; nt++)
#pragma unroll
            for (int e = 0; e < 4; e++) d[nt][e] = 0.f;

#pragma unroll 1
        for (int chunk = 0; chunk < 4; chunk++) {
            __syncthreads();
            for (int u = warp; u < 64; u += 16) {
                int kgl = u >> 2, nb = u & 3;
                int n = (nb << 5) + lane;
                int t = t0 + n;
                float v[8];
#pragma unroll
                for (int j = 0; j < 8; j++) {
                    int kg = chunk * 128 + kgl * 8 + j;
                    int ic = kg >> 1, tap = kg & 1;
                    int ts = t - 1 + tap;
                    v[j] = (ts >= 0) ? x[((b * 256 + ic) << 14) + ts] : 0.f;
                }
                uint32_t ph[4], pl[4];
#pragma unroll
                for (int m = 0; m < 4; m++)
                    split2(v[2 * m], v[2 * m + 1], ph[m], pl[m]);
                *(uint4*)(BhS + n * 136 + kgl * 8) = make_uint4(ph[0], ph[1], ph[2], ph[3]);
                *(uint4*)(BlS + n * 136 + kgl * 8) = make_uint4(pl[0], pl[1], pl[2], pl[3]);
            }
            __syncthreads();

            uint32_t choff = (uint32_t)(chunk * 64 * 136 * 2);
#pragma unroll 1
            for (int ks = 0; ks < 8; ks++) {
                uint32_t offA = choff + (uint32_t)(ks * 16 * 2);
                uint32_t offB = (uint32_t)(ks * 16 * 2);
                uint32_t ah[4], al[4];
                ldsm_x4(ah, aBase + offA);
                ldsm_x4(al, aBase + A_LO + offA);
#pragma unroll
                for (int p = 0; p < 2; p++) {
                    uint32_t bh[4], bl[4];
                    ldsm_x4(bh, bBase[p] + offB);
                    ldsm_x4(bl, bBase[p] + B_LO + offB);
                    int e0 = 2 * p, e1 = 2 * p + 1;
                    mma_bf16(d[e0], ah[0], ah[1], ah[2], ah[3], bh[0], bh[1]);
                    mma_bf16(d[e0], ah[0], ah[1], ah[2], ah[3], bl[0], bl[1]);
                    mma_bf16(d[e0], al[0], al[1], al[2], al[3], bh[0], bh[1]);
                    mma_bf16(d[e1], ah[0], ah[1], ah[2], ah[3], bh[2], bh[3]);
                    mma_bf16(d[e1], ah[0], ah[1], ah[2], ah[3], bl[2], bl[3]);
                    mma_bf16(d[e1], al[0], al[1], al[2], al[3], bh[2], bh[3]);
                }
            }
        }

#pragma unroll
        for (int hh = 0; hh < 2; hh++) {
            int oc = mt * 16 + rl + hh * 8;
            float bv = bb[oc];
            size_t hbase = ((size_t)(b * 64 + oc) << 14) + t0;
            float* hp = &g_h[0][hbase];
#pragma unroll
            for (int nt = 0; nt < 4; nt++) {
                int col = tg * 32 + (nt >> 1) * 16 + (nt & 1) * 8 + q;
                float2 v = make_float2(tanhf(d[nt][hh * 2] + bv),
                                       tanhf(d[nt][hh * 2 + 1] + bv));
                *(float2*)(hp + col) = v;
                uint32_t hi, lo;
                split2(v.x, v.y, hi, lo);
                *(uint32_t*)(g_hbh[0] + hbase + col) = hi;
                *(uint32_t*)(g_hbl[0] + hbase + col) = lo;
            }
        }
    }
}

// =======================================================================
// Kernel 2 (v11): gate — staging is pure bf16 copies (h + c prepped).
// =======================================================================
#define GATE_SMEM 222208
__global__ __launch_bounds__(512) void gate_kernel(
    int layer, int dil, int hsel,
    const float* __restrict__ W_dil, const float* __restrict__ b_dil,
    const float* __restrict__ W_c, const float* __restrict__ b_c)
{
    extern __shared__ float smf[];
    char* smem = (char*)smf;

    int tid = threadIdx.x;
    int lane = tid & 31, warp = tid >> 5;
    const float* Wd = W_dil + layer * 24576;
    const float* Wc = W_c + layer * 10240;
    const __nv_bfloat16* hbh = g_hbh[hsel];
    const __nv_bfloat16* hbl = g_hbl[hsel];

    __nv_bfloat16* Ah_s = (__nv_bfloat16*)(smem + 1024);
    __nv_bfloat16* Al_s = (__nv_bfloat16*)(smem + 72704);
    __nv_bfloat16* Bh_s = (__nv_bfloat16*)(smem + 144384);
    __nv_bfloat16* Bl_s = (__nv_bfloat16*)(smem + 183296);
    float* ys = (float*)(smem + 144384);    // overlay on B region

    if (tid < 128) {
        int g = (tid & 1) ? 64 + (tid >> 1) : (tid >> 1);
        smf[tid] = b_dil[layer * 128 + g] + b_c[layer * 128 + g];
    }
    for (int i = tid; i < 128 * 272; i += 512) {
        int pg = i / 272, k = i - pg * 272;
        int g = (pg & 1) ? 64 + (pg >> 1) : (pg >> 1);
        float w = (k < 192) ? Wd[g * 192 + (k & 63) * 3 + (k >> 6)]
                            : Wc[g * 80 + (k - 192)];
        __nv_bfloat16 wh = __float2bfloat16(w);
        Ah_s[pg * 280 + k] = wh;
        Al_s[pg * 280 + k] = __float2bfloat16(w - __bfloat162float(wh));
    }
    __syncthreads();

    int m0 = (warp & 7) * 16;
    int n0 = (warp >> 3) * 64;
    int r0 = m0 + (lane >> 2);
    int q = (lane & 3) * 2;

    uint32_t sb = smem_u32(smem);
    uint32_t aBase = sb + 1024 +
        (uint32_t)(((m0 + (lane & 15)) * 280 + (lane >> 4) * 8) * 2);
    const uint32_t A_LO = 71680;
    uint32_t bBase[4];
#pragma unroll
    for (int p = 0; p < 4; p++) {
        int n = n0 + ((lane >> 4) & 1) * 8 + (lane & 7) + 16 * p;
        bBase[p] = sb + 144384 + (uint32_t)((n * 152) * 2 + (lane & 8) * 2);
    }
    const uint32_t B_LO = 38912;

    for (int tile = blockIdx.x; tile < NB * 128; tile += gridDim.x) {
        int b = tile >> 7;
        int t0 = (tile & 127) << 7;

        float d[8][4];
#pragma unroll
        for (int nt = 0; nt < 8; nt++)
#pragma unroll
            for (int e = 0; e < 4; e++) d[nt][e] = 0.f;

#pragma unroll 1
        for (int chunk = 0; chunk < 2; chunk++) {
            int ug0 = chunk ? 18 : 0;
            int ug1 = chunk ? 34 : 18;
            for (int u = ug0 * 4 + warp; u < ug1 * 4; u += 16) {
                int kg = u >> 2, nb = u & 3;
                int n = (nb << 5) + lane;
                int t = t0 + n;
                int klocal = kg * 8 - (chunk ? 144 : 0);
                const __nv_bfloat16 *sh, *sl;
                bool zero = false;
                if (kg < 24) {
                    int tap = kg >> 3, rb = (kg & 7) << 3;
                    int ts = t - (2 - tap) * dil;
                    if (ts < 0) zero = true;
                    size_t off = ((size_t)(b * 64 + rb) << 14) + ts;
                    sh = hbh + off;
                    sl = hbl + off;
                } else {
                    int cb = (kg - 24) << 3;
                    size_t off = ((size_t)(b * 80 + cb) << 14) + t;
                    sh = g_cbh + off;
                    sl = g_cbl + off;
                }
                __nv_bfloat16 th[8], tl[8];
                if (zero) {
#pragma unroll
                    for (int j = 0; j < 8; j++) { th[j] = __nv_bfloat16(0.f); tl[j] = __nv_bfloat16(0.f); }
                } else {
#pragma unroll
                    for (int j = 0; j < 8; j++) {
                        th[j] = sh[(size_t)j << 14];
                        tl[j] = sl[(size_t)j << 14];
                    }
                }
                *(uint4*)(Bh_s + n * 152 + klocal) = *(uint4*)th;
                *(uint4*)(Bl_s + n * 152 + klocal) = *(uint4*)tl;
            }
            __syncthreads();

            int nk = chunk ? 8 : 9;
            int kAbase = chunk ? 144 : 0;
#pragma unroll 1
            for (int ks = 0; ks < nk; ks++) {
                uint32_t offA = (uint32_t)((kAbase + ks * 16) * 2);
                uint32_t offB = (uint32_t)(ks * 16 * 2);
                uint32_t ah[4], al[4];
                ldsm_x4(ah, aBase + offA);
                ldsm_x4(al, aBase + A_LO + offA);
#pragma unroll
                for (int p = 0; p < 4; p++) {
                    uint32_t bh[4], bl[4];
                    ldsm_x4(bh, bBase[p] + offB);
                    ldsm_x4(bl, bBase[p] + B_LO + offB);
                    int e0 = 2 * p, e1 = 2 * p + 1;
                    mma_bf16(d[e0], ah[0], ah[1], ah[2], ah[3], bh[0], bh[1]);
                    mma_bf16(d[e0], ah[0], ah[1], ah[2], ah[3], bl[0], bl[1]);
                    mma_bf16(d[e0], al[0], al[1], al[2], al[3], bh[0], bh[1]);
                    mma_bf16(d[e1], ah[0], ah[1], ah[2], ah[3], bh[2], bh[3]);
                    mma_bf16(d[e1], ah[0], ah[1], ah[2], ah[3], bl[2], bl[3]);
                    mma_bf16(d[e1], al[0], al[1], al[2], al[3], bh[2], bh[3]);
                }
            }
            __syncthreads();
        }

#pragma unroll
        for (int nt = 0; nt < 8; nt++) {
            int col = n0 + nt * 8 + q;
            *(float2*)(ys + r0 * 132 + col)       = make_float2(d[nt][0], d[nt][1]);
            *(float2*)(ys + (r0 + 8) * 132 + col) = make_float2(d[nt][2], d[nt][3]);
        }
        __syncthreads();

        // ---- z = tanh(a)*sigmoid(b); convert to bf16 hi/lo; coalesced rows ----
        {
            int i = tid >> 3;
            int qb = tid & 7;
            float ba = smf[2 * i], bb = smf[2 * i + 1];
            const float* ya = ys + (2 * i) * 132 + qb * 16;
            const float* yb = ys + (2 * i + 1) * 132 + qb * 16;
            __nv_bfloat16 hbuf[16], lbuf[16];
#pragma unroll
            for (int e = 0; e < 4; e++) {
                float4 av = *(const float4*)(ya + e * 4);
                float4 bv = *(const float4*)(yb + e * 4);
                float zf[4];
                zf[0] = tanhf(av.x + ba) * sigmoidf_(bv.x + bb);
                zf[1] = tanhf(av.y + ba) * sigmoidf_(bv.y + bb);
                zf[2] = tanhf(av.z + ba) * sigmoidf_(bv.z + bb);
                zf[3] = tanhf(av.w + ba) * sigmoidf_(bv.w + bb);
#pragma unroll
                for (int j = 0; j < 4; j++) {
                    __nv_bfloat16 hh = __float2bfloat16(zf[j]);
                    hbuf[e * 4 + j] = hh;
                    lbuf[e * 4 + j] = __float2bfloat16(zf[j] - __bfloat162float(hh));
                }
            }
            size_t base = (((size_t)layer * NB + b) * 64 + i) * (size_t)T_LEN
                        + t0 + qb * 16;
            *(uint4*)(g_zbh + base)     = ((uint4*)hbuf)[0];
            *(uint4*)(g_zbh + base + 8) = ((uint4*)hbuf)[1];
            *(uint4*)(g_zbl + base)     = ((uint4*)lbuf)[0];
            *(uint4*)(g_zbl + base + 8) = ((uint4*)lbuf)[1];
        }
        __syncthreads();
    }
}

// =======================================================================
// Kernel 3: out-update; also emits h' as bf16 hi/lo.
// =======================================================================
#define OUT_SMEM 68096
__global__ __launch_bounds__(512, 2) void out_kernel(
    int layer, int hsel,
    const float* __restrict__ W_out, const float* __restrict__ b_out)
{
    extern __shared__ float smf[];
    char* smem = (char*)smf;

    int tid = threadIdx.x;
    int lane = tid & 31, warp = tid >> 5;
    const float* Wo = W_out + layer * 4096;
    const float* h_in = g_h[hsel];
    float* h_out = g_h[1 - hsel];
    __nv_bfloat16* hbh_o = g_hbh[1 - hsel];
    __nv_bfloat16* hbl_o = g_hbl[1 - hsel];

    float* bo_s = smf;   // 64
    __nv_bfloat16* Ah = (__nv_bfloat16*)(smem + 512);
    __nv_bfloat16* Al = (__nv_bfloat16*)(smem + 11776);
    __nv_bfloat16* Bh = (__nv_bfloat16*)(smem + 23040);
    __nv_bfloat16* Bl = (__nv_bfloat16*)(smem + 45568);
    const uint32_t A_LO = 11264, B_LO = 22528;

    if (tid < 64) bo_s[tid] = b_out[layer * 64 + tid];
    for (int i = tid; i < 64 * 64; i += 512) {
        int m = i >> 6, k = i & 63;
        float w = Wo[(m << 6) + k];
        __nv_bfloat16 wh = __float2bfloat16(w);
        Ah[m * 88 + k] = wh;
        Al[m * 88 + k] = __float2bfloat16(w - __bfloat162float(wh));
    }
    __syncthreads();

    int q = (lane & 3) * 2;
    int rl = lane >> 2;
    uint32_t sb = smem_u32(smem);
    uint32_t aLaneOff = (uint32_t)(((lane & 15) * 88 + (lane >> 4) * 8) * 2);
    uint32_t bLaneOff = (uint32_t)(((((lane >> 4) & 1) * 8 + (lane & 7)) * 88) * 2
                                   + (lane & 8) * 2);
    size_t zlb = ((size_t)layer * NB) * 64 * (size_t)T_LEN;

    for (int tile = blockIdx.x; tile < NB * 128; tile += gridDim.x) {
        int b = tile >> 7;
        int t0 = (tile & 127) << 7;
        size_t zbase = zlb + (size_t)b * 64 * T_LEN;

        __syncthreads();   // prev tile's B reads done
        for (int u = warp; u < 32; u += 16) {
            int kg = u >> 2, nb = u & 3;
            int n = (nb << 5) + lane;
            int t = t0 + n;
            const __nv_bfloat16* zh = g_zbh + zbase + ((size_t)(kg * 8) << 14) + t;
            const __nv_bfloat16* zl = g_zbl + zbase + ((size_t)(kg * 8) << 14) + t;
            __nv_bfloat16 th[8], tl[8];
#pragma unroll
            for (int j = 0; j < 8; j++) {
                th[j] = zh[(size_t)j << 14];
                tl[j] = zl[(size_t)j << 14];
            }
            *(uint4*)(Bh + n * 88 + kg * 8) = *(uint4*)th;
            *(uint4*)(Bl + n * 88 + kg * 8) = *(uint4*)tl;
        }
        __syncthreads();

        {
            int u = warp;
            int mt = u >> 2, ng = u & 3;
            int m0 = mt << 4, n0g = ng << 5;
            int r0 = m0 + rl;

            uint32_t aBase = sb + 512 + (uint32_t)(m0 * 88 * 2) + aLaneOff;
            uint32_t bBase = sb + 23040 + (uint32_t)(n0g * 88 * 2) + bLaneOff;

            float d[4][4];
#pragma unroll
            for (int nt = 0; nt < 4; nt++)
#pragma unroll
                for (int e = 0; e < 4; e++) d[nt][e] = 0.f;

#pragma unroll
            for (int ks = 0; ks < 4; ks++) {
                uint32_t off = (uint32_t)(ks * 16 * 2);
                uint32_t ah[4], al[4];
                ldsm_x4(ah, aBase + off);
                ldsm_x4(al, aBase + A_LO + off);
#pragma unroll
                for (int p = 0; p < 2; p++) {
                    uint32_t bh[4], bl[4];
                    uint32_t bp = bBase + (uint32_t)(16 * p * 88 * 2) + off;
                    ldsm_x4(bh, bp);
                    ldsm_x4(bl, bp + B_LO);
                    int e0 = 2 * p, e1 = 2 * p + 1;
                    mma_bf16(d[e0], ah[0], ah[1], ah[2], ah[3], bh[0], bh[1]);
                    mma_bf16(d[e0], ah[0], ah[1], ah[2], ah[3], bl[0], bl[1]);
                    mma_bf16(d[e0], al[0], al[1], al[2], al[3], bh[0], bh[1]);
                    mma_bf16(d[e1], ah[0], ah[1], ah[2], ah[3], bh[2], bh[3]);
                    mma_bf16(d[e1], ah[0], ah[1], ah[2], ah[3], bl[2], bl[3]);
                    mma_bf16(d[e1], al[0], al[1], al[2], al[3], bh[2], bh[3]);
                }
            }

#pragma unroll
            for (int hh = 0; hh < 2; hh++) {
                int oc = r0 + hh * 8;
                float bov = bo_s[oc];
                size_t hbase = ((size_t)(b * 64 + oc) << 14) + t0 + n0g + q;
                const float* hip = h_in + hbase;
                float* hop = h_out + hbase;
#pragma unroll
                for (int nt = 0; nt < 4; nt++) {
                    float2 hv = *(const float2*)(hip + nt * 8);
                    float2 v = make_float2(
                        (d[nt][hh * 2] + bov + hv.x) * SQRT_HALF_F,
                        (d[nt][hh * 2 + 1] + bov + hv.y) * SQRT_HALF_F);
                    *(float2*)(hop + nt * 8) = v;
                    uint32_t hi, lo;
                    split2(v.x, v.y, hi, lo);
                    *(uint32_t*)(hbh_o + hbase + nt * 8) = hi;
                    *(uint32_t*)(hbl_o + hbase + nt * 8) = lo;
                }
            }
        }
    }
}

// =======================================================================
// Kernel 4: skipgemm — skips = sum_l scaled Wskip_l @ z_l. (unchanged)
// =======================================================================
#define SKG_SMEM 209920
__global__ __launch_bounds__(512) void skipgemm_kernel()
{
    extern __shared__ float smf[];
    char* smem = (char*)smf;

    int tid = threadIdx.x;
    int lane = tid & 31, warp = tid >> 5;

    float* bb = smf;
    __nv_bfloat16* AhS = (__nv_bfloat16*)(smem + 1024);
    __nv_bfloat16* AlS = (__nv_bfloat16*)(smem + 70656);
    __nv_bfloat16* BhS = (__nv_bfloat16*)(smem + 140288);
    __nv_bfloat16* BlS = (__nv_bfloat16*)(smem + 175104);
    const uint32_t A_LO = 69632, B_LO = 34816;

    if (tid < 256) bb[tid] = g_bskc[tid];

    int mt = warp;
    int q = (lane & 3) * 2;
    int rl = lane >> 2;

    uint32_t sb = smem_u32(smem);
    uint32_t aBase = sb + 1024 +
        (uint32_t)(((mt * 16 + (lane & 15)) * 136 + (lane >> 4) * 8) * 2);
    uint32_t bBase[8];
#pragma unroll
    for (int p = 0; p < 8; p++) {
        int n = ((lane >> 4) & 1) * 8 + (lane & 7) + 16 * p;
        bBase[p] = sb + 140288 + (uint32_t)((n * 136) * 2 + (lane & 8) * 2);
    }

    for (int tile = blockIdx.x; tile < NB * 128; tile += gridDim.x) {
        int b = tile >> 7;
        int t0 = (tile & 127) << 7;

        float d[16][4];
#pragma unroll
        for (int nt = 0; nt < 16; nt++)
#pragma unroll
            for (int e = 0; e < 4; e++) d[nt][e] = 0.f;

#pragma unroll 1
        for (int chunk = 0; chunk < 10; chunk++) {
            __syncthreads();
            {
                const uint4* gh = (const uint4*)g_swh[chunk];
                const uint4* gl = (const uint4*)g_swl[chunk];
                uint4* sh = (uint4*)AhS;
                uint4* sl = (uint4*)AlS;
                for (int i = tid; i < 4352; i += 512) {
                    sh[i] = gh[i];
                    sl[i] = gl[i];
                }
            }
            for (int u = warp; u < 64; u += 16) {
                int kg = u >> 2, nb = u & 3;
                int n = (nb << 5) + lane;
                int t = t0 + n;
                int l = chunk * 2 + (kg >> 3);
                int ch0 = (kg & 7) << 3;
                size_t zbase = (((size_t)l * NB + b) * 64 + ch0) * (size_t)T_LEN + t;
                const __nv_bfloat16* zh = g_zbh + zbase;
                const __nv_bfloat16* zl = g_zbl + zbase;
                __nv_bfloat16 th[8], tl[8];
#pragma unroll
                for (int j = 0; j < 8; j++) {
                    th[j] = zh[(size_t)j << 14];
                    tl[j] = zl[(size_t)j << 14];
                }
                *(uint4*)(BhS + n * 136 + kg * 8) = *(uint4*)th;
                *(uint4*)(BlS + n * 136 + kg * 8) = *(uint4*)tl;
            }
            __syncthreads();

#pragma unroll 1
            for (int ks = 0; ks < 8; ks++) {
                uint32_t off = (uint32_t)(ks * 16 * 2);
                uint32_t ah[4], al[4];
                ldsm_x4(ah, aBase + off);
                ldsm_x4(al, aBase + A_LO + off);
#pragma unroll
                for (int p = 0; p < 8; p++) {
                    uint32_t bh[4], bl[4];
                    ldsm_x4(bh, bBase[p] + off);
                    ldsm_x4(bl, bBase[p] + B_LO + off);
                    int e0 = 2 * p, e1 = 2 * p + 1;
                    mma_bf16(d[e0], ah[0], ah[1], ah[2], ah[3], bh[0], bh[1]);
                    mma_bf16(d[e0], ah[0], ah[1], ah[2], ah[3], bl[0], bl[1]);
                    mma_bf16(d[e0], al[0], al[1], al[2], al[3], bh[0], bh[1]);
                    mma_bf16(d[e1], ah[0], ah[1], ah[2], ah[3], bh[2], bh[3]);
                    mma_bf16(d[e1], ah[0], ah[1], ah[2], ah[3], bl[2], bl[3]);
                    mma_bf16(d[e1], al[0], al[1], al[2], al[3], bh[2], bh[3]);
                }
            }
        }

#pragma unroll
        for (int hh = 0; hh < 2; hh++) {
            int oc = mt * 16 + rl + hh * 8;
            float bv = bb[oc];
            float* op = g_skip + ((b * 256 + oc) << 14) + t0;
#pragma unroll
            for (int nt = 0; nt < 16; nt++) {
                int col = (nt >> 1) * 16 + (nt & 1) * 8 + q;
                *(float2*)(op + col) =
                    make_float2(d[nt][hh * 2] + bv, d[nt][hh * 2 + 1] + bv);
            }
        }
    }
}

// =======================================================================
// Kernel 5 (HMMA + ldmatrix): dense 256x256, prepped weights. (unchanged)
// =======================================================================
#define DENSE_SMEM 209920
__global__ __launch_bounds__(512) void dense_hmma_kernel(
    int stage, float* __restrict__ final_out, const float* __restrict__ bias)
{
    extern __shared__ float smf[];
    char* smem = (char*)smf;

    int tid = threadIdx.x;
    int lane = tid & 31, warp = tid >> 5;

    const float* in = (stage == 0) ? g_skip : g_tmp;
    float* out = (stage == 0) ? g_tmp : final_out;

    float* bb = smf;
    __nv_bfloat16* AhS = (__nv_bfloat16*)(smem + 1024);
    __nv_bfloat16* AlS = (__nv_bfloat16*)(smem + 70656);
    __nv_bfloat16* BhS = (__nv_bfloat16*)(smem + 140288);
    __nv_bfloat16* BlS = (__nv_bfloat16*)(smem + 175104);
    const uint32_t A_LO = 69632, B_LO = 34816;

    if (tid < 256) bb[tid] = bias[tid];

    int mt = warp;
    int q = (lane & 3) * 2;
    int rl = lane >> 2;

    uint32_t sb = smem_u32(smem);
    uint32_t aBase = sb + 1024 +
        (uint32_t)(((mt * 16 + (lane & 15)) * 136 + (lane >> 4) * 8) * 2);
    uint32_t bBase[8];
#pragma unroll
    for (int p = 0; p < 8; p++) {
        int n = ((lane >> 4) & 1) * 8 + (lane & 7) + 16 * p;
        bBase[p] = sb + 140288 + (uint32_t)((n * 136) * 2 + (lane & 8) * 2);
    }

    for (int tile = blockIdx.x; tile < NB * 128; tile += gridDim.x) {
        int b = tile >> 7;
        int t0 = (tile & 127) << 7;

        float d[16][4];
#pragma unroll
        for (int nt = 0; nt < 16; nt++)
#pragma unroll
            for (int e = 0; e < 4; e++) d[nt][e] = 0.f;

#pragma unroll 1
        for (int chunk = 0; chunk < 2; chunk++) {
            __syncthreads();
            {
                const uint4* gh = (const uint4*)g_dwh[stage][chunk];
                const uint4* gl = (const uint4*)g_dwl[stage][chunk];
                uint4* sh = (uint4*)AhS;
                uint4* sl = (uint4*)AlS;
                for (int i = tid; i < 4352; i += 512) {
                    sh[i] = gh[i];
                    sl[i] = gl[i];
                }
            }
            for (int u = warp; u < 64; u += 16) {
                int kg = u >> 2, nb = u & 3;
                int n = (nb << 5) + lane;
                int t = t0 + n;
                const float* ip = in + ((b * 256 + chunk * 128 + kg * 8) << 14) + t;
                float v[8];
#pragma unroll
                for (int j = 0; j < 8; j++) {
                    float xv = ip[j << 14];
                    v[j] = (stage == 0) ? fmaxf(xv, 0.f) : xv;
                }
                uint32_t ph[4], pl[4];
#pragma unroll
                for (int m = 0; m < 4; m++)
                    split2(v[2 * m], v[2 * m + 1], ph[m], pl[m]);
                *(uint4*)(BhS + n * 136 + kg * 8) = make_uint4(ph[0], ph[1], ph[2], ph[3]);
                *(uint4*)(BlS + n * 136 + kg * 8) = make_uint4(pl[0], pl[1], pl[2], pl[3]);
            }
            __syncthreads();

#pragma unroll 1
            for (int ks = 0; ks < 8; ks++) {
                uint32_t off = (uint32_t)(ks * 16 * 2);
                uint32_t ah[4], al[4];
                ldsm_x4(ah, aBase + off);
                ldsm_x4(al, aBase + A_LO + off);
#pragma unroll
                for (int p = 0; p < 8; p++) {
                    uint32_t bh[4], bl[4];
                    ldsm_x4(bh, bBase[p] + off);
                    ldsm_x4(bl, bBase[p] + B_LO + off);
                    int e0 = 2 * p, e1 = 2 * p + 1;
                    mma_bf16(d[e0], ah[0], ah[1], ah[2], ah[3], bh[0], bh[1]);
                    mma_bf16(d[e0], ah[0], ah[1], ah[2], ah[3], bl[0], bl[1]);
                    mma_bf16(d[e0], al[0], al[1], al[2], al[3], bh[0], bh[1]);
                    mma_bf16(d[e1], ah[0], ah[1], ah[2], ah[3], bh[2], bh[3]);
                    mma_bf16(d[e1], ah[0], ah[1], ah[2], ah[3], bl[2], bl[3]);
                    mma_bf16(d[e1], al[0], al[1], al[2], al[3], bh[2], bh[3]);
                }
            }
        }

#pragma unroll
        for (int hh = 0; hh < 2; hh++) {
            int oc = mt * 16 + rl + hh * 8;
            float bv = bb[oc];
            float* op = out + ((b * 256 + oc) << 14) + t0;
#pragma unroll
            for (int nt = 0; nt < 16; nt++) {
                int col = (nt >> 1) * 16 + (nt & 1) * 8 + q;
                float2 v = make_float2(d[nt][hh * 2] + bv, d[nt][hh * 2 + 1] + bv);
                if (stage == 0) {
                    v.x = fmaxf(v.x, 0.f);
                    v.y = fmaxf(v.y, 0.f);
                }
                *(float2*)(op + col) = v;
            }
        }
    }
}

// =======================================================================
extern "C" void kernel_launch(void* const* d_in, const int* in_sizes, int n_in,
                              void* d_out, int out_size)
{
    const float* x       = (const float*)d_in[0];
    const float* c       = (const float*)d_in[1];
    const float* W_first = (const float*)d_in[2];
    const float* b_first = (const float*)d_in[3];
    const float* W_dil   = (const float*)d_in[4];
    const float* b_dil   = (const float*)d_in[5];
    const float* W_c     = (const float*)d_in[6];
    const float* b_c     = (const float*)d_in[7];
    const float* W_skip  = (const float*)d_in[8];
    const float* b_skip  = (const float*)d_in[9];
    const float* W_out   = (const float*)d_in[10];
    const float* b_out   = (const float*)d_in[11];
    const float* W_last1 = (const float*)d_in[12];
    const float* b_last1 = (const float*)d_in[13];
    const float* W_last2 = (const float*)d_in[14];
    const float* b_last2 = (const float*)d_in[15];
    float* out = (float*)d_out;

    cudaFuncSetAttribute(first_hmma_kernel, cudaFuncAttributeMaxDynamicSharedMemorySize, FIRST_SMEM);
    cudaFuncSetAttribute(gate_kernel,   cudaFuncAttributeMaxDynamicSharedMemorySize, GATE_SMEM);
    cudaFuncSetAttribute(out_kernel,    cudaFuncAttributeMaxDynamicSharedMemorySize, OUT_SMEM);
    cudaFuncSetAttribute(skipgemm_kernel, cudaFuncAttributeMaxDynamicSharedMemorySize, SKG_SMEM);
    cudaFuncSetAttribute(dense_hmma_kernel, cudaFuncAttributeMaxDynamicSharedMemorySize, DENSE_SMEM);

    int dev = 0;
    cudaGetDevice(&dev);
    int sm_count = 148;
    cudaDeviceGetAttribute(&sm_count, cudaDevAttrMultiProcessorCount, dev);
    int grid1 = sm_count;
    int grid2 = 2 * sm_count;

    prep_dense_kernel<<<256, 512>>>(W_last1, W_last2);
    prep_skipw_kernel<<<(256 * 1280 + 511) / 512, 512>>>(W_skip, b_skip);
    prep_c_kernel<<<(NB * 80 * T_LEN / 4 + 511) / 512, 512>>>(c);
    first_hmma_kernel<<<grid1, 512, FIRST_SMEM>>>(x, W_first, b_first);

    for (int l = 0; l < 20; l++) {
        int dil = 1 << (l % 10);
        int hsel = l & 1;
        gate_kernel<<<grid1, 512, GATE_SMEM>>>(l, dil, hsel,
                                               W_dil, b_dil, W_c, b_c);
        out_kernel<<<grid2, 512, OUT_SMEM>>>(l, hsel, W_out, b_out);
    }

    skipgemm_kernel<<<grid1, 512, SKG_SMEM>>>();
    dense_hmma_kernel<<<grid1, 512, DENSE_SMEM>>>(0, out, b_last1);
    dense_hmma_kernel<<<grid1, 512, DENSE_SMEM>>>(1, out, b_last2);
}

// round 17
// speedup vs baseline: 1.1407x; 1.1407x over previous
#include <cuda_runtime.h>
#include <cuda_bf16.h>
#include <stdint.h>
#include <math.h>

#define T_LEN 16384
#define NB 4

static __device__ __forceinline__ float sigmoidf_(float v) {
    return 1.0f / (1.0f + __expf(-v));
}

#define SQRT_HALF_F 0.70710678118654752f

// bf16 HMMA m16n8k16 (base-target PTX)
static __device__ __forceinline__ void mma_bf16(
    float* d, uint32_t a0, uint32_t a1, uint32_t a2, uint32_t a3,
    uint32_t b0, uint32_t b1)
{
    asm volatile(
        "mma.sync.aligned.m16n8k16.row.col.f32.bf16.bf16.f32 "
        "{%0,%1,%2,%3}, {%4,%5,%6,%7}, {%8,%9}, {%0,%1,%2,%3};"
        : "+f"(d[0]), "+f"(d[1]), "+f"(d[2]), "+f"(d[3])
        : "r"(a0), "r"(a1), "r"(a2), "r"(a3), "r"(b0), "r"(b1));
}
// ldmatrix x4 (base PTX sm_75+)
static __device__ __forceinline__ void ldsm_x4(uint32_t* r, uint32_t addr) {
    asm volatile(
        "ldmatrix.sync.aligned.m8n8.x4.shared.b16 {%0,%1,%2,%3}, [%4];"
        : "=r"(r[0]), "=r"(r[1]), "=r"(r[2]), "=r"(r[3]) : "r"(addr));
}
static __device__ __forceinline__ uint32_t pk_bf2(float a, float b) {
    __nv_bfloat162 t;
    t.x = __float2bfloat16(a);
    t.y = __float2bfloat16(b);
    return *(uint32_t*)&t;
}
static __device__ __forceinline__ uint32_t smem_u32(const void* p) {
    uint32_t a;
    asm("{ .reg .u64 t; cvta.to.shared.u64 t, %1; cvt.u32.u64 %0, t; }"
        : "=r"(a) : "l"(p));
    return a;
}
static __device__ __forceinline__ void split2(float a, float b,
                                              uint32_t& hi, uint32_t& lo) {
    __nv_bfloat16 h0 = __float2bfloat16(a);
    __nv_bfloat16 h1 = __float2bfloat16(b);
    hi = pk_bf2(a, b);
    lo = pk_bf2(a - __bfloat162float(h0), b - __bfloat162float(h1));
}

// ---------------- scratch (allocation-free: __device__ globals) ----------------
__device__ float g_h[2][NB * 64 * T_LEN];     // residual ping-pong
__device__ float g_skip[NB * 256 * T_LEN];    // skip accumulator (written once)
__device__ float g_tmp[NB * 256 * T_LEN];     // final intermediate
// z storage (all layers), bf16 hi/lo, layout [((l*NB + b)*64 + ch)][t]
__device__ __nv_bfloat16 g_zbh[20 * NB * 64 * T_LEN];
__device__ __nv_bfloat16 g_zbl[20 * NB * 64 * T_LEN];
// prepped dense weights: [stage][chunk][oc*136 + klocal]
__device__ __nv_bfloat16 g_dwh[2][2][256 * 136];
__device__ __nv_bfloat16 g_dwl[2][2][256 * 136];
// prepped scaled skip weights: [chunk 0..9][sc*136 + klocal], combined bias
__device__ __nv_bfloat16 g_swh[10][256 * 136];
__device__ __nv_bfloat16 g_swl[10][256 * 136];
__device__ float g_bskc[256];

// telescoped scale: s_l multiplied by sqrt(1/2)^e, e = 19 for l=0, 20-l for l>=1
static __device__ __forceinline__ float skip_scale(int l) {
    int e = (l == 0) ? 19 : (20 - l);
    return exp2f(-0.5f * (float)e);
}

// =======================================================================
// Kernel 0a: prep dense weights
// =======================================================================
__global__ void prep_dense_kernel(const float* __restrict__ W1,
                                  const float* __restrict__ W2)
{
    int i = blockIdx.x * blockDim.x + threadIdx.x;
    if (i >= 2 * 256 * 256) return;
    int stage = i >> 16;
    int oc = (i >> 8) & 255;
    int k = i & 255;
    float w = (stage ? W2 : W1)[oc * 256 + k];
    __nv_bfloat16 wh = __float2bfloat16(w);
    int chunk = k >> 7, kl = k & 127;
    g_dwh[stage][chunk][oc * 136 + kl] = wh;
    g_dwl[stage][chunk][oc * 136 + kl] = __float2bfloat16(w - __bfloat162float(wh));
}

// =======================================================================
// Kernel 0b: prep scaled skip weights + combined bias
// =======================================================================
__global__ void prep_skipw_kernel(const float* __restrict__ W_skip,
                                  const float* __restrict__ b_skip)
{
    int i = blockIdx.x * blockDim.x + threadIdx.x;
    if (i < 256 * 1280) {
        int sc = i / 1280, k = i - sc * 1280;
        int l = k >> 6, r = k & 63;
        float w = W_skip[l * 16384 + sc * 64 + r] * skip_scale(l);
        __nv_bfloat16 wh = __float2bfloat16(w);
        int chunk = k >> 7, kl = k & 127;
        g_swh[chunk][sc * 136 + kl] = wh;
        g_swl[chunk][sc * 136 + kl] = __float2bfloat16(w - __bfloat162float(wh));
    }
    if (i < 256) {
        float s = 0.f;
        for (int l = 0; l < 20; l++)
            s += skip_scale(l) * b_skip[l * 256 + i];
        g_bskc[i] = s;
    }
}

// =======================================================================
// Kernel 1 (HMMA + ldmatrix): first conv (R11/R15 version)
// =======================================================================
#define FIRST_SMEM 209920
__global__ __launch_bounds__(512) void first_hmma_kernel(
    const float* __restrict__ x, const float* __restrict__ Wf,
    const float* __restrict__ bf)
{
    extern __shared__ float smf[];
    char* smem = (char*)smf;

    int tid = threadIdx.x;
    int lane = tid & 31, warp = tid >> 5;

    float* bb = smf;    // 64
    __nv_bfloat16* AhS = (__nv_bfloat16*)(smem + 1024);
    __nv_bfloat16* AlS = (__nv_bfloat16*)(smem + 70656);
    __nv_bfloat16* BhS = (__nv_bfloat16*)(smem + 140288);
    __nv_bfloat16* BlS = (__nv_bfloat16*)(smem + 175104);
    const uint32_t A_LO = 69632, B_LO = 34816;

    if (tid < 64) bb[tid] = bf[tid];
    for (int i = tid; i < 64 * 512; i += 512) {
        int oc = i >> 9, k = i & 511;
        int chunk = k >> 7, kl = k & 127;
        float w = Wf[oc * 512 + k];
        __nv_bfloat16 wh = __float2bfloat16(w);
        AhS[(chunk * 64 + oc) * 136 + kl] = wh;
        AlS[(chunk * 64 + oc) * 136 + kl] = __float2bfloat16(w - __bfloat162float(wh));
    }
    __syncthreads();

    int mt = warp & 3;
    int tg = warp >> 2;
    int q = (lane & 3) * 2;
    int rl = lane >> 2;

    uint32_t sb = smem_u32(smem);
    uint32_t aBase = sb + 1024 +
        (uint32_t)(((mt * 16 + (lane & 15)) * 136 + (lane >> 4) * 8) * 2);
    uint32_t bBase[2];
#pragma unroll
    for (int p = 0; p < 2; p++) {
        int n = tg * 32 + ((lane >> 4) & 1) * 8 + (lane & 7) + 16 * p;
        bBase[p] = sb + 140288 + (uint32_t)((n * 136) * 2 + (lane & 8) * 2);
    }

    for (int tile = blockIdx.x; tile < NB * 128; tile += gridDim.x) {
        int b = tile >> 7;
        int t0 = (tile & 127) << 7;

        float d[4][4];
#pragma unroll
        for (int nt = 0; nt < 4; nt++)
#pragma unroll
            for (int e = 0; e < 4; e++) d[nt][e] = 0.f;

#pragma unroll 1
        for (int chunk = 0; chunk < 4; chunk++) {
            __syncthreads();
            for (int u = warp; u < 64; u += 16) {
                int kgl = u >> 2, nb = u & 3;
                int n = (nb << 5) + lane;
                int t = t0 + n;
                float v[8];
#pragma unroll
                for (int j = 0; j < 8; j++) {
                    int kg = chunk * 128 + kgl * 8 + j;
                    int ic = kg >> 1, tap = kg & 1;
                    int ts = t - 1 + tap;
                    v[j] = (ts >= 0) ? x[((b * 256 + ic) << 14) + ts] : 0.f;
                }
                uint32_t ph[4], pl[4];
#pragma unroll
                for (int m = 0; m < 4; m++)
                    split2(v[2 * m], v[2 * m + 1], ph[m], pl[m]);
                *(uint4*)(BhS + n * 136 + kgl * 8) = make_uint4(ph[0], ph[1], ph[2], ph[3]);
                *(uint4*)(BlS + n * 136 + kgl * 8) = make_uint4(pl[0], pl[1], pl[2], pl[3]);
            }
            __syncthreads();

            uint32_t choff = (uint32_t)(chunk * 64 * 136 * 2);
#pragma unroll 1
            for (int ks = 0; ks < 8; ks++) {
                uint32_t offA = choff + (uint32_t)(ks * 16 * 2);
                uint32_t offB = (uint32_t)(ks * 16 * 2);
                uint32_t ah[4], al[4];
                ldsm_x4(ah, aBase + offA);
                ldsm_x4(al, aBase + A_LO + offA);
#pragma unroll
                for (int p = 0; p < 2; p++) {
                    uint32_t bh[4], bl[4];
                    ldsm_x4(bh, bBase[p] + offB);
                    ldsm_x4(bl, bBase[p] + B_LO + offB);
                    int e0 = 2 * p, e1 = 2 * p + 1;
                    mma_bf16(d[e0], ah[0], ah[1], ah[2], ah[3], bh[0], bh[1]);
                    mma_bf16(d[e0], ah[0], ah[1], ah[2], ah[3], bl[0], bl[1]);
                    mma_bf16(d[e0], al[0], al[1], al[2], al[3], bh[0], bh[1]);
                    mma_bf16(d[e1], ah[0], ah[1], ah[2], ah[3], bh[2], bh[3]);
                    mma_bf16(d[e1], ah[0], ah[1], ah[2], ah[3], bl[2], bl[3]);
                    mma_bf16(d[e1], al[0], al[1], al[2], al[3], bh[2], bh[3]);
                }
            }
        }

#pragma unroll
        for (int hh = 0; hh < 2; hh++) {
            int oc = mt * 16 + rl + hh * 8;
            float bv = bb[oc];
            float* hp = &g_h[0][((b * 64 + oc) << 14) + t0];
#pragma unroll
            for (int nt = 0; nt < 4; nt++) {
                int col = tg * 32 + (nt >> 1) * 16 + (nt & 1) * 8 + q;
                float2 v = make_float2(tanhf(d[nt][hh * 2] + bv),
                                       tanhf(d[nt][hh * 2 + 1] + bv));
                *(float2*)(hp + col) = v;
            }
        }
    }
}

// =======================================================================
// Kernel 2 (v12): gate — R15 + register prefetch of chunk 1 staging.
// =======================================================================
#define GATE_SMEM 222208
__global__ __launch_bounds__(512) void gate_kernel(
    int layer, int dil, int hsel,
    const float* __restrict__ c,
    const float* __restrict__ W_dil, const float* __restrict__ b_dil,
    const float* __restrict__ W_c, const float* __restrict__ b_c)
{
    extern __shared__ float smf[];
    char* smem = (char*)smf;

    int tid = threadIdx.x;
    int lane = tid & 31, warp = tid >> 5;
    const float* Wd = W_dil + layer * 24576;
    const float* Wc = W_c + layer * 10240;
    const float* h_in = g_h[hsel];

    __nv_bfloat16* Ah_s = (__nv_bfloat16*)(smem + 1024);
    __nv_bfloat16* Al_s = (__nv_bfloat16*)(smem + 72704);
    __nv_bfloat16* Bh_s = (__nv_bfloat16*)(smem + 144384);
    __nv_bfloat16* Bl_s = (__nv_bfloat16*)(smem + 183296);
    float* ys = (float*)(smem + 144384);    // overlay on B region

    if (tid < 128) {
        int g = (tid & 1) ? 64 + (tid >> 1) : (tid >> 1);
        smf[tid] = b_dil[layer * 128 + g] + b_c[layer * 128 + g];
    }
    for (int i = tid; i < 128 * 272; i += 512) {
        int pg = i / 272, k = i - pg * 272;
        int g = (pg & 1) ? 64 + (pg >> 1) : (pg >> 1);
        float w = (k < 192) ? Wd[g * 192 + (k & 63) * 3 + (k >> 6)]
                            : Wc[g * 80 + (k - 192)];
        __nv_bfloat16 wh = __float2bfloat16(w);
        Ah_s[pg * 280 + k] = wh;
        Al_s[pg * 280 + k] = __float2bfloat16(w - __bfloat162float(wh));
    }
    __syncthreads();

    int m0 = (warp & 7) * 16;
    int n0 = (warp >> 3) * 64;
    int r0 = m0 + (lane >> 2);
    int q = (lane & 3) * 2;

    uint32_t sb = smem_u32(smem);
    uint32_t aBase = sb + 1024 +
        (uint32_t)(((m0 + (lane & 15)) * 280 + (lane >> 4) * 8) * 2);
    const uint32_t A_LO = 71680;
    uint32_t bBase[4];
#pragma unroll
    for (int p = 0; p < 4; p++) {
        int n = n0 + ((lane >> 4) & 1) * 8 + (lane & 7) + 16 * p;
        bBase[p] = sb + 144384 + (uint32_t)((n * 152) * 2 + (lane & 8) * 2);
    }
    const uint32_t B_LO = 38912;

    for (int tile = blockIdx.x; tile < NB * 128; tile += gridDim.x) {
        int b = tile >> 7;
        int t0 = (tile & 127) << 7;

        float d[8][4];
#pragma unroll
        for (int nt = 0; nt < 8; nt++)
#pragma unroll
            for (int e = 0; e < 4; e++) d[nt][e] = 0.f;

        // ---- stage chunk 0 (kg 0..17) directly to smem ----
        for (int u = warp; u < 72; u += 16) {
            int kg = u >> 2, nb = u & 3;
            int n = (nb << 5) + lane;
            int t = t0 + n;
            float v[8];
            {
                int tap = kg >> 3, rb = (kg & 7) << 3;
                int ts = t - (2 - tap) * dil;
                const float* hp = h_in + ((b * 64 + rb) << 14) + ts;
                if (ts >= 0) {
#pragma unroll
                    for (int j = 0; j < 8; j++) v[j] = hp[j << 14];
                } else {
#pragma unroll
                    for (int j = 0; j < 8; j++) v[j] = 0.f;
                }
            }
            uint32_t ph[4], pl[4];
#pragma unroll
            for (int m = 0; m < 4; m++)
                split2(v[2 * m], v[2 * m + 1], ph[m], pl[m]);
            int klocal = kg * 8;
            *(uint4*)(Bh_s + n * 152 + klocal) = make_uint4(ph[0], ph[1], ph[2], ph[3]);
            *(uint4*)(Bl_s + n * 152 + klocal) = make_uint4(pl[0], pl[1], pl[2], pl[3]);
        }
        __syncthreads();

        // ---- prefetch chunk 1 (kg 18..33): 4 units/warp into registers ----
        float pf[4][8];
#pragma unroll
        for (int i = 0; i < 4; i++) {
            int u = 72 + warp + 16 * i;
            int kg = u >> 2, nb = u & 3;
            int n = (nb << 5) + lane;
            int t = t0 + n;
            if (kg < 24) {
                int tap = kg >> 3, rb = (kg & 7) << 3;
                int ts = t - (2 - tap) * dil;
                const float* hp = h_in + ((b * 64 + rb) << 14) + ts;
                if (ts >= 0) {
#pragma unroll
                    for (int j = 0; j < 8; j++) pf[i][j] = hp[j << 14];
                } else {
#pragma unroll
                    for (int j = 0; j < 8; j++) pf[i][j] = 0.f;
                }
            } else {
                int cb = (kg - 24) << 3;
                const float* cp = c + ((b * 80 + cb) << 14) + t;
#pragma unroll
                for (int j = 0; j < 8; j++) pf[i][j] = cp[j << 14];
            }
        }

        // ---- mma chunk 0 (9 ksteps) — prefetch latency hides under this ----
#pragma unroll 1
        for (int ks = 0; ks < 9; ks++) {
            uint32_t offA = (uint32_t)((ks * 16) * 2);
            uint32_t offB = (uint32_t)(ks * 16 * 2);
            uint32_t ah[4], al[4];
            ldsm_x4(ah, aBase + offA);
            ldsm_x4(al, aBase + A_LO + offA);
#pragma unroll
            for (int p = 0; p < 4; p++) {
                uint32_t bh[4], bl[4];
                ldsm_x4(bh, bBase[p] + offB);
                ldsm_x4(bl, bBase[p] + B_LO + offB);
                int e0 = 2 * p, e1 = 2 * p + 1;
                mma_bf16(d[e0], ah[0], ah[1], ah[2], ah[3], bh[0], bh[1]);
                mma_bf16(d[e0], ah[0], ah[1], ah[2], ah[3], bl[0], bl[1]);
                mma_bf16(d[e0], al[0], al[1], al[2], al[3], bh[0], bh[1]);
                mma_bf16(d[e1], ah[0], ah[1], ah[2], ah[3], bh[2], bh[3]);
                mma_bf16(d[e1], ah[0], ah[1], ah[2], ah[3], bl[2], bl[3]);
                mma_bf16(d[e1], al[0], al[1], al[2], al[3], bh[2], bh[3]);
            }
        }
        __syncthreads();

        // ---- store prefetched chunk 1 to smem ----
#pragma unroll
        for (int i = 0; i < 4; i++) {
            int u = 72 + warp + 16 * i;
            int kg = u >> 2, nb = u & 3;
            int n = (nb << 5) + lane;
            uint32_t ph[4], pl[4];
#pragma unroll
            for (int m = 0; m < 4; m++)
                split2(pf[i][2 * m], pf[i][2 * m + 1], ph[m], pl[m]);
            int klocal = kg * 8 - 144;
            *(uint4*)(Bh_s + n * 152 + klocal) = make_uint4(ph[0], ph[1], ph[2], ph[3]);
            *(uint4*)(Bl_s + n * 152 + klocal) = make_uint4(pl[0], pl[1], pl[2], pl[3]);
        }
        __syncthreads();

        // ---- mma chunk 1 (8 ksteps, kAbase 144) ----
#pragma unroll 1
        for (int ks = 0; ks < 8; ks++) {
            uint32_t offA = (uint32_t)((144 + ks * 16) * 2);
            uint32_t offB = (uint32_t)(ks * 16 * 2);
            uint32_t ah[4], al[4];
            ldsm_x4(ah, aBase + offA);
            ldsm_x4(al, aBase + A_LO + offA);
#pragma unroll
            for (int p = 0; p < 4; p++) {
                uint32_t bh[4], bl[4];
                ldsm_x4(bh, bBase[p] + offB);
                ldsm_x4(bl, bBase[p] + B_LO + offB);
                int e0 = 2 * p, e1 = 2 * p + 1;
                mma_bf16(d[e0], ah[0], ah[1], ah[2], ah[3], bh[0], bh[1]);
                mma_bf16(d[e0], ah[0], ah[1], ah[2], ah[3], bl[0], bl[1]);
                mma_bf16(d[e0], al[0], al[1], al[2], al[3], bh[0], bh[1]);
                mma_bf16(d[e1], ah[0], ah[1], ah[2], ah[3], bh[2], bh[3]);
                mma_bf16(d[e1], ah[0], ah[1], ah[2], ah[3], bl[2], bl[3]);
                mma_bf16(d[e1], al[0], al[1], al[2], al[3], bh[2], bh[3]);
            }
        }
        __syncthreads();

        // ---- dump y to smem (overlay on B region) ----
#pragma unroll
        for (int nt = 0; nt < 8; nt++) {
            int col = n0 + nt * 8 + q;
            *(float2*)(ys + r0 * 132 + col)       = make_float2(d[nt][0], d[nt][1]);
            *(float2*)(ys + (r0 + 8) * 132 + col) = make_float2(d[nt][2], d[nt][3]);
        }
        __syncthreads();

        // ---- z = tanh(a)*sigmoid(b); convert to bf16 hi/lo; coalesced rows ----
        {
            int i = tid >> 3;
            int qb = tid & 7;
            float ba = smf[2 * i], bb = smf[2 * i + 1];
            const float* ya = ys + (2 * i) * 132 + qb * 16;
            const float* yb = ys + (2 * i + 1) * 132 + qb * 16;
            __nv_bfloat16 hbuf[16], lbuf[16];
#pragma unroll
            for (int e = 0; e < 4; e++) {
                float4 av = *(const float4*)(ya + e * 4);
                float4 bv = *(const float4*)(yb + e * 4);
                float zf[4];
                zf[0] = tanhf(av.x + ba) * sigmoidf_(bv.x + bb);
                zf[1] = tanhf(av.y + ba) * sigmoidf_(bv.y + bb);
                zf[2] = tanhf(av.z + ba) * sigmoidf_(bv.z + bb);
                zf[3] = tanhf(av.w + ba) * sigmoidf_(bv.w + bb);
#pragma unroll
                for (int j = 0; j < 4; j++) {
                    __nv_bfloat16 hh = __float2bfloat16(zf[j]);
                    hbuf[e * 4 + j] = hh;
                    lbuf[e * 4 + j] = __float2bfloat16(zf[j] - __bfloat162float(hh));
                }
            }
            size_t base = (((size_t)layer * NB + b) * 64 + i) * (size_t)T_LEN
                        + t0 + qb * 16;
            *(uint4*)(g_zbh + base)     = ((uint4*)hbuf)[0];
            *(uint4*)(g_zbh + base + 8) = ((uint4*)hbuf)[1];
            *(uint4*)(g_zbl + base)     = ((uint4*)lbuf)[0];
            *(uint4*)(g_zbl + base + 8) = ((uint4*)lbuf)[1];
        }
        __syncthreads();
    }
}

// =======================================================================
// Kernel 3: out-update only (R15 version).
// =======================================================================
#define OUT_SMEM 68096
__global__ __launch_bounds__(512, 2) void out_kernel(
    int layer, int hsel,
    const float* __restrict__ W_out, const float* __restrict__ b_out)
{
    extern __shared__ float smf[];
    char* smem = (char*)smf;

    int tid = threadIdx.x;
    int lane = tid & 31, warp = tid >> 5;
    const float* Wo = W_out + layer * 4096;
    const float* h_in = g_h[hsel];
    float* h_out = g_h[1 - hsel];

    float* bo_s = smf;   // 64
    __nv_bfloat16* Ah = (__nv_bfloat16*)(smem + 512);
    __nv_bfloat16* Al = (__nv_bfloat16*)(smem + 11776);
    __nv_bfloat16* Bh = (__nv_bfloat16*)(smem + 23040);
    __nv_bfloat16* Bl = (__nv_bfloat16*)(smem + 45568);
    const uint32_t A_LO = 11264, B_LO = 22528;

    if (tid < 64) bo_s[tid] = b_out[layer * 64 + tid];
    for (int i = tid; i < 64 * 64; i += 512) {
        int m = i >> 6, k = i & 63;
        float w = Wo[(m << 6) + k];
        __nv_bfloat16 wh = __float2bfloat16(w);
        Ah[m * 88 + k] = wh;
        Al[m * 88 + k] = __float2bfloat16(w - __bfloat162float(wh));
    }
    __syncthreads();

    int q = (lane & 3) * 2;
    int rl = lane >> 2;
    uint32_t sb = smem_u32(smem);
    uint32_t aLaneOff = (uint32_t)(((lane & 15) * 88 + (lane >> 4) * 8) * 2);
    uint32_t bLaneOff = (uint32_t)(((((lane >> 4) & 1) * 8 + (lane & 7)) * 88) * 2
                                   + (lane & 8) * 2);
    size_t zlb = ((size_t)layer * NB) * 64 * (size_t)T_LEN;

    for (int tile = blockIdx.x; tile < NB * 128; tile += gridDim.x) {
        int b = tile >> 7;
        int t0 = (tile & 127) << 7;
        size_t zbase = zlb + (size_t)b * 64 * T_LEN;

        __syncthreads();   // prev tile's B reads done
        for (int u = warp; u < 32; u += 16) {
            int kg = u >> 2, nb = u & 3;
            int n = (nb << 5) + lane;
            int t = t0 + n;
            const __nv_bfloat16* zh = g_zbh + zbase + ((size_t)(kg * 8) << 14) + t;
            const __nv_bfloat16* zl = g_zbl + zbase + ((size_t)(kg * 8) << 14) + t;
            __nv_bfloat16 th[8], tl[8];
#pragma unroll
            for (int j = 0; j < 8; j++) {
                th[j] = zh[(size_t)j << 14];
                tl[j] = zl[(size_t)j << 14];
            }
            *(uint4*)(Bh + n * 88 + kg * 8) = *(uint4*)th;
            *(uint4*)(Bl + n * 88 + kg * 8) = *(uint4*)tl;
        }
        __syncthreads();

        {
            int u = warp;
            int mt = u >> 2, ng = u & 3;
            int m0 = mt << 4, n0g = ng << 5;
            int r0 = m0 + rl;

            uint32_t aBase = sb + 512 + (uint32_t)(m0 * 88 * 2) + aLaneOff;
            uint32_t bBase = sb + 23040 + (uint32_t)(n0g * 88 * 2) + bLaneOff;

            float d[4][4];
#pragma unroll
            for (int nt = 0; nt < 4; nt++)
#pragma unroll
                for (int e = 0; e < 4; e++) d[nt][e] = 0.f;

#pragma unroll
            for (int ks = 0; ks < 4; ks++) {
                uint32_t off = (uint32_t)(ks * 16 * 2);
                uint32_t ah[4], al[4];
                ldsm_x4(ah, aBase + off);
                ldsm_x4(al, aBase + A_LO + off);
#pragma unroll
                for (int p = 0; p < 2; p++) {
                    uint32_t bh[4], bl[4];
                    uint32_t bp = bBase + (uint32_t)(16 * p * 88 * 2) + off;
                    ldsm_x4(bh, bp);
                    ldsm_x4(bl, bp + B_LO);
                    int e0 = 2 * p, e1 = 2 * p + 1;
                    mma_bf16(d[e0], ah[0], ah[1], ah[2], ah[3], bh[0], bh[1]);
                    mma_bf16(d[e0], ah[0], ah[1], ah[2], ah[3], bl[0], bl[1]);
                    mma_bf16(d[e0], al[0], al[1], al[2], al[3], bh[0], bh[1]);
                    mma_bf16(d[e1], ah[0], ah[1], ah[2], ah[3], bh[2], bh[3]);
                    mma_bf16(d[e1], ah[0], ah[1], ah[2], ah[3], bl[2], bl[3]);
                    mma_bf16(d[e1], al[0], al[1], al[2], al[3], bh[2], bh[3]);
                }
            }

#pragma unroll
            for (int hh = 0; hh < 2; hh++) {
                int oc = r0 + hh * 8;
                float bov = bo_s[oc];
                const float* hip = h_in + ((b * 64 + oc) << 14) + t0 + n0g + q;
                float* hop = h_out + ((b * 64 + oc) << 14) + t0 + n0g + q;
#pragma unroll
                for (int nt = 0; nt < 4; nt++) {
                    float2 hv = *(const float2*)(hip + nt * 8);
                    *(float2*)(hop + nt * 8) = make_float2(
                        (d[nt][hh * 2] + bov + hv.x) * SQRT_HALF_F,
                        (d[nt][hh * 2 + 1] + bov + hv.y) * SQRT_HALF_F);
                }
            }
        }
    }
}

// =======================================================================
// Kernel 4: skipgemm — skips = sum_l scaled Wskip_l @ z_l. (R15 version)
// =======================================================================
#define SKG_SMEM 209920
__global__ __launch_bounds__(512) void skipgemm_kernel()
{
    extern __shared__ float smf[];
    char* smem = (char*)smf;

    int tid = threadIdx.x;
    int lane = tid & 31, warp = tid >> 5;

    float* bb = smf;
    __nv_bfloat16* AhS = (__nv_bfloat16*)(smem + 1024);
    __nv_bfloat16* AlS = (__nv_bfloat16*)(smem + 70656);
    __nv_bfloat16* BhS = (__nv_bfloat16*)(smem + 140288);
    __nv_bfloat16* BlS = (__nv_bfloat16*)(smem + 175104);
    const uint32_t A_LO = 69632, B_LO = 34816;

    if (tid < 256) bb[tid] = g_bskc[tid];

    int mt = warp;
    int q = (lane & 3) * 2;
    int rl = lane >> 2;

    uint32_t sb = smem_u32(smem);
    uint32_t aBase = sb + 1024 +
        (uint32_t)(((mt * 16 + (lane & 15)) * 136 + (lane >> 4) * 8) * 2);
    uint32_t bBase[8];
#pragma unroll
    for (int p = 0; p < 8; p++) {
        int n = ((lane >> 4) & 1) * 8 + (lane & 7) + 16 * p;
        bBase[p] = sb + 140288 + (uint32_t)((n * 136) * 2 + (lane & 8) * 2);
    }

    for (int tile = blockIdx.x; tile < NB * 128; tile += gridDim.x) {
        int b = tile >> 7;
        int t0 = (tile & 127) << 7;

        float d[16][4];
#pragma unroll
        for (int nt = 0; nt < 16; nt++)
#pragma unroll
            for (int e = 0; e < 4; e++) d[nt][e] = 0.f;

#pragma unroll 1
        for (int chunk = 0; chunk < 10; chunk++) {
            __syncthreads();
            {
                const uint4* gh = (const uint4*)g_swh[chunk];
                const uint4* gl = (const uint4*)g_swl[chunk];
                uint4* sh = (uint4*)AhS;
                uint4* sl = (uint4*)AlS;
                for (int i = tid; i < 4352; i += 512) {
                    sh[i] = gh[i];
                    sl[i] = gl[i];
                }
            }
            for (int u = warp; u < 64; u += 16) {
                int kg = u >> 2, nb = u & 3;
                int n = (nb << 5) + lane;
                int t = t0 + n;
                int l = chunk * 2 + (kg >> 3);
                int ch0 = (kg & 7) << 3;
                size_t zbase = (((size_t)l * NB + b) * 64 + ch0) * (size_t)T_LEN + t;
                const __nv_bfloat16* zh = g_zbh + zbase;
                const __nv_bfloat16* zl = g_zbl + zbase;
                __nv_bfloat16 th[8], tl[8];
#pragma unroll
                for (int j = 0; j < 8; j++) {
                    th[j] = zh[(size_t)j << 14];
                    tl[j] = zl[(size_t)j << 14];
                }
                *(uint4*)(BhS + n * 136 + kg * 8) = *(uint4*)th;
                *(uint4*)(BlS + n * 136 + kg * 8) = *(uint4*)tl;
            }
            __syncthreads();

#pragma unroll 1
            for (int ks = 0; ks < 8; ks++) {
                uint32_t off = (uint32_t)(ks * 16 * 2);
                uint32_t ah[4], al[4];
                ldsm_x4(ah, aBase + off);
                ldsm_x4(al, aBase + A_LO + off);
#pragma unroll
                for (int p = 0; p < 8; p++) {
                    uint32_t bh[4], bl[4];
                    ldsm_x4(bh, bBase[p] + off);
                    ldsm_x4(bl, bBase[p] + B_LO + off);
                    int e0 = 2 * p, e1 = 2 * p + 1;
                    mma_bf16(d[e0], ah[0], ah[1], ah[2], ah[3], bh[0], bh[1]);
                    mma_bf16(d[e0], ah[0], ah[1], ah[2], ah[3], bl[0], bl[1]);
                    mma_bf16(d[e0], al[0], al[1], al[2], al[3], bh[0], bh[1]);
                    mma_bf16(d[e1], ah[0], ah[1], ah[2], ah[3], bh[2], bh[3]);
                    mma_bf16(d[e1], ah[0], ah[1], ah[2], ah[3], bl[2], bl[3]);
                    mma_bf16(d[e1], al[0], al[1], al[2], al[3], bh[2], bh[3]);
                }
            }
        }

#pragma unroll
        for (int hh = 0; hh < 2; hh++) {
            int oc = mt * 16 + rl + hh * 8;
            float bv = bb[oc];
            float* op = g_skip + ((b * 256 + oc) << 14) + t0;
#pragma unroll
            for (int nt = 0; nt < 16; nt++) {
                int col = (nt >> 1) * 16 + (nt & 1) * 8 + q;
                *(float2*)(op + col) =
                    make_float2(d[nt][hh * 2] + bv, d[nt][hh * 2 + 1] + bv);
            }
        }
    }
}

// =======================================================================
// Kernel 5 (HMMA + ldmatrix): dense 256x256, prepped weights. (R15 version)
// =======================================================================
#define DENSE_SMEM 209920
__global__ __launch_bounds__(512) void dense_hmma_kernel(
    int stage, float* __restrict__ final_out, const float* __restrict__ bias)
{
    extern __shared__ float smf[];
    char* smem = (char*)smf;

    int tid = threadIdx.x;
    int lane = tid & 31, warp = tid >> 5;

    const float* in = (stage == 0) ? g_skip : g_tmp;
    float* out = (stage == 0) ? g_tmp : final_out;

    float* bb = smf;
    __nv_bfloat16* AhS = (__nv_bfloat16*)(smem + 1024);
    __nv_bfloat16* AlS = (__nv_bfloat16*)(smem + 70656);
    __nv_bfloat16* BhS = (__nv_bfloat16*)(smem + 140288);
    __nv_bfloat16* BlS = (__nv_bfloat16*)(smem + 175104);
    const uint32_t A_LO = 69632, B_LO = 34816;

    if (tid < 256) bb[tid] = bias[tid];

    int mt = warp;
    int q = (lane & 3) * 2;
    int rl = lane >> 2;

    uint32_t sb = smem_u32(smem);
    uint32_t aBase = sb + 1024 +
        (uint32_t)(((mt * 16 + (lane & 15)) * 136 + (lane >> 4) * 8) * 2);
    uint32_t bBase[8];
#pragma unroll
    for (int p = 0; p < 8; p++) {
        int n = ((lane >> 4) & 1) * 8 + (lane & 7) + 16 * p;
        bBase[p] = sb + 140288 + (uint32_t)((n * 136) * 2 + (lane & 8) * 2);
    }

    for (int tile = blockIdx.x; tile < NB * 128; tile += gridDim.x) {
        int b = tile >> 7;
        int t0 = (tile & 127) << 7;

        float d[16][4];
#pragma unroll
        for (int nt = 0; nt < 16; nt++)
#pragma unroll
            for (int e = 0; e < 4; e++) d[nt][e] = 0.f;

#pragma unroll 1
        for (int chunk = 0; chunk < 2; chunk++) {
            __syncthreads();
            {
                const uint4* gh = (const uint4*)g_dwh[stage][chunk];
                const uint4* gl = (const uint4*)g_dwl[stage][chunk];
                uint4* sh = (uint4*)AhS;
                uint4* sl = (uint4*)AlS;
                for (int i = tid; i < 4352; i += 512) {
                    sh[i] = gh[i];
                    sl[i] = gl[i];
                }
            }
            for (int u = warp; u < 64; u += 16) {
                int kg = u >> 2, nb = u & 3;
                int n = (nb << 5) + lane;
                int t = t0 + n;
                const float* ip = in + ((b * 256 + chunk * 128 + kg * 8) << 14) + t;
                float v[8];
#pragma unroll
                for (int j = 0; j < 8; j++) {
                    float xv = ip[j << 14];
                    v[j] = (stage == 0) ? fmaxf(xv, 0.f) : xv;
                }
                uint32_t ph[4], pl[4];
#pragma unroll
                for (int m = 0; m < 4; m++)
                    split2(v[2 * m], v[2 * m + 1], ph[m], pl[m]);
                *(uint4*)(BhS + n * 136 + kg * 8) = make_uint4(ph[0], ph[1], ph[2], ph[3]);
                *(uint4*)(BlS + n * 136 + kg * 8) = make_uint4(pl[0], pl[1], pl[2], pl[3]);
            }
            __syncthreads();

#pragma unroll 1
            for (int ks = 0; ks < 8; ks++) {
                uint32_t off = (uint32_t)(ks * 16 * 2);
                uint32_t ah[4], al[4];
                ldsm_x4(ah, aBase + off);
                ldsm_x4(al, aBase + A_LO + off);
#pragma unroll
                for (int p = 0; p < 8; p++) {
                    uint32_t bh[4], bl[4];
                    ldsm_x4(bh, bBase[p] + off);
                    ldsm_x4(bl, bBase[p] + B_LO + off);
                    int e0 = 2 * p, e1 = 2 * p + 1;
                    mma_bf16(d[e0], ah[0], ah[1], ah[2], ah[3], bh[0], bh[1]);
                    mma_bf16(d[e0], ah[0], ah[1], ah[2], ah[3], bl[0], bl[1]);
                    mma_bf16(d[e0], al[0], al[1], al[2], al[3], bh[0], bh[1]);
                    mma_bf16(d[e1], ah[0], ah[1], ah[2], ah[3], bh[2], bh[3]);
                    mma_bf16(d[e1], ah[0], ah[1], ah[2], ah[3], bl[2], bl[3]);
                    mma_bf16(d[e1], al[0], al[1], al[2], al[3], bh[2], bh[3]);
                }
            }
        }

#pragma unroll
        for (int hh = 0; hh < 2; hh++) {
            int oc = mt * 16 + rl + hh * 8;
            float bv = bb[oc];
            float* op = out + ((b * 256 + oc) << 14) + t0;
#pragma unroll
            for (int nt = 0; nt < 16; nt++) {
                int col = (nt >> 1) * 16 + (nt & 1) * 8 + q;
                float2 v = make_float2(d[nt][hh * 2] + bv, d[nt][hh * 2 + 1] + bv);
                if (stage == 0) {
                    v.x = fmaxf(v.x, 0.f);
                    v.y = fmaxf(v.y, 0.f);
                }
                *(float2*)(op + col) = v;
            }
        }
    }
}

// =======================================================================
extern "C" void kernel_launch(void* const* d_in, const int* in_sizes, int n_in,
                              void* d_out, int out_size)
{
    const float* x       = (const float*)d_in[0];
    const float* c       = (const float*)d_in[1];
    const float* W_first = (const float*)d_in[2];
    const float* b_first = (const float*)d_in[3];
    const float* W_dil   = (const float*)d_in[4];
    const float* b_dil   = (const float*)d_in[5];
    const float* W_c     = (const float*)d_in[6];
    const float* b_c     = (const float*)d_in[7];
    const float* W_skip  = (const float*)d_in[8];
    const float* b_skip  = (const float*)d_in[9];
    const float* W_out   = (const float*)d_in[10];
    const float* b_out   = (const float*)d_in[11];
    const float* W_last1 = (const float*)d_in[12];
    const float* b_last1 = (const float*)d_in[13];
    const float* W_last2 = (const float*)d_in[14];
    const float* b_last2 = (const float*)d_in[15];
    float* out = (float*)d_out;

    cudaFuncSetAttribute(first_hmma_kernel, cudaFuncAttributeMaxDynamicSharedMemorySize, FIRST_SMEM);
    cudaFuncSetAttribute(gate_kernel,   cudaFuncAttributeMaxDynamicSharedMemorySize, GATE_SMEM);
    cudaFuncSetAttribute(out_kernel,    cudaFuncAttributeMaxDynamicSharedMemorySize, OUT_SMEM);
    cudaFuncSetAttribute(skipgemm_kernel, cudaFuncAttributeMaxDynamicSharedMemorySize, SKG_SMEM);
    cudaFuncSetAttribute(dense_hmma_kernel, cudaFuncAttributeMaxDynamicSharedMemorySize, DENSE_SMEM);

    int dev = 0;
    cudaGetDevice(&dev);
    int sm_count = 148;
    cudaDeviceGetAttribute(&sm_count, cudaDevAttrMultiProcessorCount, dev);
    int grid1 = sm_count;
    int grid2 = 2 * sm_count;

    prep_dense_kernel<<<256, 512>>>(W_last1, W_last2);
    prep_skipw_kernel<<<(256 * 1280 + 511) / 512, 512>>>(W_skip, b_skip);
    first_hmma_kernel<<<grid1, 512, FIRST_SMEM>>>(x, W_first, b_first);

    for (int l = 0; l < 20; l++) {
        int dil = 1 << (l % 10);
        int hsel = l & 1;
        gate_kernel<<<grid1, 512, GATE_SMEM>>>(l, dil, hsel, c,
                                               W_dil, b_dil, W_c, b_c);
        out_kernel<<<grid2, 512, OUT_SMEM>>>(l, hsel, W_out, b_out);
    }

    skipgemm_kernel<<<grid1, 512, SKG_SMEM>>>();
    dense_hmma_kernel<<<grid1, 512, DENSE_SMEM>>>(0, out, b_last1);
    dense_hmma_kernel<<<grid1, 512, DENSE_SMEM>>>(1, out, b_last2);
}